// round 3
// baseline (speedup 1.0000x reference)
#include <cuda_runtime.h>
#include <math.h>

#define BB 16
#define Q  8400
#define CC 80
#define G  64
#define RADIUS (2.5f/32.0f)

// ---- scratch (static device globals; no runtime allocation) ----
__device__ float              g_cost[(long long)BB*G*Q];   // [b][g][q]
__device__ float              g_iou [(long long)BB*G*Q];   // [b][g][q]
__device__ unsigned long long g_mask[BB*Q];                // per-anchor GT bitmask
__device__ float              g_pen [BB*Q];                // accumulated row penalty
__device__ int                g_rowarg[BB*Q];              // argmin_g cost0[q][g]
__device__ unsigned char      g_stale[BB*Q];

// =====================================================================
// Kernel A: build cost + iou (column-major), row argmin, zero scratch
// =====================================================================
__global__ void build_cost_kernel(const float* __restrict__ logits,
                                  const float* __restrict__ boxes,
                                  const int*   __restrict__ labels,
                                  const float* __restrict__ gtboxes)
{
    int b = blockIdx.y;
    int q = blockIdx.x * blockDim.x + threadIdx.x;
    __shared__ float s_g [G*4];   // gt cxcywh
    __shared__ float s_gx[G*4];   // gt xyxy
    __shared__ float s_area[G];
    __shared__ int   s_lab[G];
    int t = threadIdx.x;
    if (t < G) {
        float4 gb = ((const float4*)gtboxes)[b*G + t];
        s_g[t*4+0]=gb.x; s_g[t*4+1]=gb.y; s_g[t*4+2]=gb.z; s_g[t*4+3]=gb.w;
        float x0=gb.x-0.5f*gb.z, y0=gb.y-0.5f*gb.w;
        float x1=gb.x+0.5f*gb.z, y1=gb.y+0.5f*gb.w;
        s_gx[t*4+0]=x0; s_gx[t*4+1]=y0; s_gx[t*4+2]=x1; s_gx[t*4+3]=y1;
        s_area[t]=(x1-x0)*(y1-y0);
        s_lab[t]=labels[b*G+t];
    }
    __syncthreads();
    if (q >= Q) return;

    float4 pb = ((const float4*)boxes)[b*Q + q];
    float ax = pb.x, ay = pb.y;
    float bx0 = pb.x-0.5f*pb.z, by0 = pb.y-0.5f*pb.w;
    float bx1 = pb.x+0.5f*pb.z, by1 = pb.y+0.5f*pb.w;
    float areaA = (bx1-bx0)*(by1-by0);

    // pass 1: geometry masks / fg
    unsigned long long iibc = 0ULL;
    bool any_ib=false, any_ic=false;
    #pragma unroll 8
    for (int g=0; g<G; g++) {
        bool ib = (ax>s_gx[g*4+0]) && (ax<s_gx[g*4+2]) &&
                  (ay>s_gx[g*4+1]) && (ay<s_gx[g*4+3]);
        float gcx=s_g[g*4+0], gcy=s_g[g*4+1];
        bool ic = (ax>gcx-RADIUS)&&(ax<gcx+RADIUS)&&
                  (ay>gcy-RADIUS)&&(ay<gcy+RADIUS);
        any_ib |= ib; any_ic |= ic;
        if (ib && ic) iibc |= (1ULL<<g);
    }
    float fgterm = (any_ib || any_ic) ? 0.0f : 10000.0f;

    const float* lrow = logits + ((long long)b*Q + q)*CC;
    float bestv = INFINITY; int bestg = 0;
    for (int g=0; g<G; g++) {
        float x = lrow[s_lab[g]];
        float p = 1.0f/(1.0f + expf(-x));
        float neg = 0.75f * p*p * (-logf(1.0f - p + 1e-8f));
        float pos = 0.25f * (1.0f-p)*(1.0f-p) * (-logf(p + 1e-8f));
        float cls = pos - neg;

        float gx0=s_gx[g*4+0], gy0=s_gx[g*4+1], gx1=s_gx[g*4+2], gy1=s_gx[g*4+3];
        float ltx=fmaxf(bx0,gx0), lty=fmaxf(by0,gy0);
        float rbx=fminf(bx1,gx1), rby=fminf(by1,gy1);
        float iw=fmaxf(rbx-ltx,0.0f), ih=fmaxf(rby-lty,0.0f);
        float inter = iw*ih;
        float uni   = areaA + s_area[g] - inter;
        float iou   = inter/uni;
        float ex0=fminf(bx0,gx0), ey0=fminf(by0,gy0);
        float ex1=fmaxf(bx1,gx1), ey1=fmaxf(by1,gy1);
        float encl = fmaxf(ex1-ex0,0.0f)*fmaxf(ey1-ey0,0.0f);
        float giou = iou - (encl - uni)/encl;

        float cost = cls - 3.0f*giou
                   + (((iibc>>g)&1ULL) ? 0.0f : 100.0f) + fgterm;
        long long idx = ((long long)b*G + g)*Q + q;
        g_cost[idx] = cost;
        g_iou [idx] = iou;
        if (cost < bestv) { bestv = cost; bestg = g; }
    }
    g_rowarg[b*Q+q] = bestg;
    g_mask  [b*Q+q] = 0ULL;
    g_pen   [b*Q+q] = 0.0f;
}

// =====================================================================
// Kernel B: per (b,g) column: dyn_k = max(trunc(sum top-10 iou),1);
// pick dyn_k smallest costs (lowest-index tie-break) -> set mask bits
// =====================================================================
#define TKB 256
__global__ void select_kernel()
{
    int b = blockIdx.x / G, g = blockIdx.x % G;
    const float* iou  = g_iou  + ((long long)b*G+g)*Q;
    const float* cost = g_cost + ((long long)b*G+g)*Q;
    __shared__ float s_buf[Q];            // reused: top10 lists then cost copy
    __shared__ float s_rv[TKB];
    __shared__ int   s_ri[TKB];
    __shared__ int   s_dynk;
    int t = threadIdx.x;

    // per-thread descending top-10 of iou column
    float top[10];
    #pragma unroll
    for (int i=0;i<10;i++) top[i] = -INFINITY;
    for (int q=t; q<Q; q+=TKB) {
        float v = iou[q];
        if (v > top[9]) {
            int i = 9;
            while (i>0 && top[i-1] < v) { top[i]=top[i-1]; i--; }
            top[i] = v;
        }
    }
    #pragma unroll
    for (int i=0;i<10;i++) s_buf[t*10+i] = top[i];
    __syncthreads();
    // tree merge of sorted-desc 10-lists
    for (int s=TKB/2; s>=1; s>>=1) {
        if (t < s) {
            float a[10], c[10], m[10];
            #pragma unroll
            for (int i=0;i<10;i++){ a[i]=s_buf[t*10+i]; c[i]=s_buf[(t+s)*10+i]; }
            int ia=0, ic=0;
            #pragma unroll
            for (int i=0;i<10;i++) m[i] = (a[ia] >= c[ic]) ? a[ia++] : c[ic++];
            #pragma unroll
            for (int i=0;i<10;i++) s_buf[t*10+i] = m[i];
        }
        __syncthreads();
    }
    if (t==0) {
        float ssum = 0.0f;
        for (int i=0;i<10;i++) ssum += s_buf[i];
        int k = (int)ssum;        // trunc toward zero
        if (k < 1) k = 1;
        s_dynk = k;
    }
    __syncthreads();
    int dynk = s_dynk;

    // cost column into smem
    for (int q=t; q<Q; q+=TKB) s_buf[q] = cost[q];
    __syncthreads();

    for (int k=0; k<dynk; k++) {
        float bv = INFINITY; int bi = Q;
        for (int q=t; q<Q; q+=TKB) {
            float v = s_buf[q];
            if (v < bv) { bv=v; bi=q; }
        }
        s_rv[t]=bv; s_ri[t]=bi;
        __syncthreads();
        for (int s=TKB/2; s>=1; s>>=1) {
            if (t < s) {
                float ov=s_rv[t+s]; int oi=s_ri[t+s];
                if (ov < s_rv[t] || (ov==s_rv[t] && oi < s_ri[t])) { s_rv[t]=ov; s_ri[t]=oi; }
            }
            __syncthreads();
        }
        if (t==0) {
            int qm = s_ri[0];
            atomicOr(&g_mask[b*Q+qm], 1ULL<<g);
            s_buf[qm] = INFINITY;
        }
        __syncthreads();
    }
}

// =====================================================================
// Kernel C: row dedup — rows with >1 matches become one-hot(row argmin)
// =====================================================================
__global__ void dedup_kernel()
{
    int i = blockIdx.x*blockDim.x + threadIdx.x;
    if (i >= BB*Q) return;
    unsigned long long m = g_mask[i];
    if (__popcll(m) > 1) {
        g_stale[i] = 1;
        g_mask[i]  = 1ULL << g_rowarg[i];
    } else {
        g_stale[i] = 0;
    }
}

// =====================================================================
// Kernel D: per-image while-loop + outputs (one block per image).
// Output layouts:
//   layoutB==0: FLOAT32 concat [sel(BQ) | asn(BQ) | mq(BG)] as float values
//   layoutB==1: byte layout    [bool8 sel (BQ bytes) | int32 asn | int32 mq]
// =====================================================================
#define TD 256
__global__ void loop_kernel(char* __restrict__ out_bytes, int layoutB)
{
    int b = blockIdx.x, t = threadIdx.x;
    unsigned long long* mask = g_mask + b*Q;
    float* pen = g_pen + b*Q;
    const float* cost = g_cost + (long long)b*G*Q;
    const int* rowarg = g_rowarg + b*Q;
    const unsigned char* stale = g_stale + b*Q;

    __shared__ int   s_cnt[G];
    __shared__ int   s_flag;
    __shared__ float s_rv[TD];
    __shared__ int   s_ri[TD];

    for (int iter=0; iter<20000; iter++) {
        if (t < G) s_cnt[t] = 0;
        if (t == 0) s_flag = 0;
        __syncthreads();
        for (int q=t; q<Q; q+=TD) {
            unsigned long long m = mask[q];
            while (m) { int g = __ffsll((long long)m)-1; atomicAdd(&s_cnt[g],1); m &= m-1; }
        }
        __syncthreads();
        if (t < G && s_cnt[t] == 0) s_flag = 1;
        __syncthreads();
        if (s_flag == 0) break;               // cond: all columns matched

        // c2 = c + 100000 * matched_rows  (row-uniform accumulation)
        for (int q=t; q<Q; q+=TD) if (mask[q]) pen[q] += 100000.0f;
        __syncthreads();

        // add col-argmin match for every unmatched column (penalty fixed)
        for (int g=0; g<G; g++) {
            if (s_cnt[g] != 0) continue;
            const float* cg = cost + (long long)g*Q;
            float bv = INFINITY; int bi = Q;
            for (int q=t; q<Q; q+=TD) {
                float v = cg[q] + pen[q];
                if (v < bv) { bv=v; bi=q; }
            }
            s_rv[t]=bv; s_ri[t]=bi;
            __syncthreads();
            for (int s=TD/2; s>=1; s>>=1) {
                if (t < s) {
                    float ov=s_rv[t+s]; int oi=s_ri[t+s];
                    if (ov < s_rv[t] || (ov==s_rv[t] && oi < s_ri[t])) { s_rv[t]=ov; s_ri[t]=oi; }
                }
                __syncthreads();
            }
            if (t==0) mask[s_ri[0]] |= (1ULL<<g);
            __syncthreads();
        }

        // fix: if any row >1 matches, reset all stale rows to one-hot(row argmin)
        if (t==0) s_flag = 0;
        __syncthreads();
        for (int q=t; q<Q; q+=TD) if (__popcll(mask[q]) > 1) s_flag = 1;
        __syncthreads();
        if (s_flag) {
            for (int q=t; q<Q; q+=TD) if (stale[q]) mask[q] = 1ULL << rowarg[q];
        }
        __syncthreads();
    }

    // ---- outputs ----
    if (layoutB) {
        unsigned char* out_sel = (unsigned char*)out_bytes;                 // bool8
        int* out_asn = (int*)(out_bytes + (size_t)BB*Q);                    // int32
        int* out_mq  = (int*)(out_bytes + (size_t)BB*Q + (size_t)4*BB*Q);   // int32
        for (int q=t; q<Q; q+=TD) {
            unsigned long long m = mask[q];
            out_sel[b*Q+q] = m ? 1 : 0;
            out_asn[b*Q+q] = m ? (__ffsll((long long)m)-1) : 0;
        }
        int wid = t/32, lane = t%32, nw = TD/32;
        for (int g=wid; g<G; g+=nw) {
            const float* cg = cost + (long long)g*Q;
            float bv = INFINITY; int bi = 0;
            for (int q=lane; q<Q; q+=32) {
                if ((mask[q]>>g) & 1ULL) {
                    float v = cg[q] + pen[q];
                    if (v < bv) { bv=v; bi=q; }
                }
            }
            for (int off=16; off; off>>=1) {
                float ov = __shfl_down_sync(0xffffffff, bv, off);
                int   oi = __shfl_down_sync(0xffffffff, bi, off);
                if (ov < bv || (ov==bv && oi < bi)) { bv=ov; bi=oi; }
            }
            if (lane==0) out_mq[b*G+g] = bi;
        }
    } else {
        // FLOAT32 concat layout
        float* out = (float*)out_bytes;
        float* out_sel = out;
        float* out_asn = out + BB*Q;
        float* out_mq  = out + 2*BB*Q;
        for (int q=t; q<Q; q+=TD) {
            unsigned long long m = mask[q];
            out_sel[b*Q+q] = m ? 1.0f : 0.0f;
            out_asn[b*Q+q] = m ? (float)(__ffsll((long long)m)-1) : 0.0f;
        }
        int wid = t/32, lane = t%32, nw = TD/32;
        for (int g=wid; g<G; g+=nw) {
            const float* cg = cost + (long long)g*Q;
            float bv = INFINITY; int bi = 0;
            for (int q=lane; q<Q; q+=32) {
                if ((mask[q]>>g) & 1ULL) {
                    float v = cg[q] + pen[q];
                    if (v < bv) { bv=v; bi=q; }
                }
            }
            for (int off=16; off; off>>=1) {
                float ov = __shfl_down_sync(0xffffffff, bv, off);
                int   oi = __shfl_down_sync(0xffffffff, bi, off);
                if (ov < bv || (ov==bv && oi < bi)) { bv=ov; bi=oi; }
            }
            if (lane==0) out_mq[b*G+g] = (float)bi;
        }
    }
}

// =====================================================================
extern "C" void kernel_launch(void* const* d_in, const int* in_sizes, int n_in,
                              void* d_out, int out_size)
{
    // Map inputs by element count (robust to metadata ordering):
    //   logits: B*Q*C = 10,752,000   boxes: B*Q*4 = 537,600
    //   labels: B*G   = 1,024        gtb:   B*G*4 = 4,096
    const float* logits = 0; const float* boxes = 0;
    const int*   labels = 0; const float* gtb   = 0;
    for (int i = 0; i < n_in; i++) {
        switch (in_sizes[i]) {
            case BB*Q*CC: logits = (const float*)d_in[i]; break;
            case BB*Q*4:  boxes  = (const float*)d_in[i]; break;
            case BB*G:    labels = (const int*)  d_in[i]; break;
            case BB*G*4:  gtb    = (const float*)d_in[i]; break;
        }
    }

    // Output layout: byte-mixed iff out_size matches the byte total; else
    // a single-dtype concat of 269,824 elements, written as float32.
    int layoutB = (out_size == BB*Q + 4*BB*Q + 4*BB*G) ? 1 : 0;

    dim3 gA((Q + 255)/256, BB);
    build_cost_kernel<<<gA, 256>>>(logits, boxes, labels, gtb);
    select_kernel<<<BB*G, TKB>>>();
    dedup_kernel<<<(BB*Q + 255)/256, 256>>>();
    loop_kernel<<<BB, TD>>>((char*)d_out, layoutB);
}

// round 4
// speedup vs baseline: 1.0464x; 1.0464x over previous
#include <cuda_runtime.h>
#include <math.h>

#define BB 16
#define Q  8400
#define CC 80
#define G  64
#define RADIUS (2.5f/32.0f)

// ---- scratch (static device globals; no runtime allocation) ----
__device__ float              g_cost[(long long)BB*G*Q];   // [b][g][q]
__device__ float              g_iou [(long long)BB*G*Q];   // [b][g][q]
__device__ unsigned long long g_mask[BB*Q];                // per-anchor GT bitmask
__device__ float              g_pen [BB*Q];                // accumulated row penalty
__device__ int                g_rowarg[BB*Q];              // argmin_g cost0[q][g]

// =====================================================================
// Kernel A: build cost + iou (column-major), row argmin, init scratch.
// Logits staged through shared memory (coalesced GMEM, padded SMEM).
// =====================================================================
#define TA 128
__global__ void build_cost_kernel(const float* __restrict__ logits,
                                  const float* __restrict__ boxes,
                                  const int*   __restrict__ labels,
                                  const float* __restrict__ gtboxes)
{
    int b = blockIdx.y;
    int qbase = blockIdx.x * TA;
    int t = threadIdx.x;

    __shared__ float s_row[TA*81];   // 81-padded logits rows
    __shared__ float s_g [G*4];      // gt cxcywh
    __shared__ float s_gx[G*4];      // gt xyxy
    __shared__ float s_area[G];
    __shared__ int   s_lab[G];

    if (t < G) {
        float4 gb = ((const float4*)gtboxes)[b*G + t];
        s_g[t*4+0]=gb.x; s_g[t*4+1]=gb.y; s_g[t*4+2]=gb.z; s_g[t*4+3]=gb.w;
        float x0=gb.x-0.5f*gb.z, y0=gb.y-0.5f*gb.w;
        float x1=gb.x+0.5f*gb.z, y1=gb.y+0.5f*gb.w;
        s_gx[t*4+0]=x0; s_gx[t*4+1]=y0; s_gx[t*4+2]=x1; s_gx[t*4+3]=y1;
        s_area[t]=(x1-x0)*(y1-y0);
        s_lab[t]=labels[b*G+t];
    }

    // coalesced stage of up to TA logits rows
    int nrows = Q - qbase; if (nrows > TA) nrows = TA;
    const float* lbase = logits + ((long long)b*Q + qbase)*CC;
    for (int idx = t; idx < nrows*CC; idx += TA) {
        int row = idx / CC, col = idx - row*CC;
        s_row[row*81 + col] = lbase[idx];
    }
    __syncthreads();

    int q = qbase + t;
    if (q >= Q) return;

    float4 pb = ((const float4*)boxes)[b*Q + q];
    float ax = pb.x, ay = pb.y;
    float bx0 = pb.x-0.5f*pb.z, by0 = pb.y-0.5f*pb.w;
    float bx1 = pb.x+0.5f*pb.z, by1 = pb.y+0.5f*pb.w;
    float areaA = (bx1-bx0)*(by1-by0);

    // geometry masks / fg
    unsigned long long iibc = 0ULL;
    bool any_ib=false, any_ic=false;
    #pragma unroll 8
    for (int g=0; g<G; g++) {
        bool ib = (ax>s_gx[g*4+0]) && (ax<s_gx[g*4+2]) &&
                  (ay>s_gx[g*4+1]) && (ay<s_gx[g*4+3]);
        float gcx=s_g[g*4+0], gcy=s_g[g*4+1];
        bool ic = (ax>gcx-RADIUS)&&(ax<gcx+RADIUS)&&
                  (ay>gcy-RADIUS)&&(ay<gcy+RADIUS);
        any_ib |= ib; any_ic |= ic;
        if (ib && ic) iibc |= (1ULL<<g);
    }
    float fgterm = (any_ib || any_ic) ? 0.0f : 10000.0f;

    const float* lrow = s_row + t*81;
    float bestv = INFINITY; int bestg = 0;
    for (int g=0; g<G; g++) {
        float x = lrow[s_lab[g]];
        float p = 1.0f/(1.0f + expf(-x));
        float neg = 0.75f * p*p * (-logf(1.0f - p + 1e-8f));
        float pos = 0.25f * (1.0f-p)*(1.0f-p) * (-logf(p + 1e-8f));
        float cls = pos - neg;

        float gx0=s_gx[g*4+0], gy0=s_gx[g*4+1], gx1=s_gx[g*4+2], gy1=s_gx[g*4+3];
        float ltx=fmaxf(bx0,gx0), lty=fmaxf(by0,gy0);
        float rbx=fminf(bx1,gx1), rby=fminf(by1,gy1);
        float iw=fmaxf(rbx-ltx,0.0f), ih=fmaxf(rby-lty,0.0f);
        float inter = iw*ih;
        float uni   = areaA + s_area[g] - inter;
        float iou   = inter/uni;
        float ex0=fminf(bx0,gx0), ey0=fminf(by0,gy0);
        float ex1=fmaxf(bx1,gx1), ey1=fmaxf(by1,gy1);
        float encl = fmaxf(ex1-ex0,0.0f)*fmaxf(ey1-ey0,0.0f);
        float giou = iou - (encl - uni)/encl;

        float cost = cls - 3.0f*giou
                   + (((iibc>>g)&1ULL) ? 0.0f : 100.0f) + fgterm;
        long long idx = ((long long)b*G + g)*Q + q;
        g_cost[idx] = cost;
        g_iou [idx] = iou;
        if (cost < bestv) { bestv = cost; bestg = g; }
    }
    g_rowarg[b*Q+q] = bestg;
    g_mask  [b*Q+q] = 0ULL;
    g_pen   [b*Q+q] = 0.0f;
}

// =====================================================================
// Kernel B: per (b,g) column, single pass each over iou and cost:
//  dyn_k = clamp(trunc(sum top-10 iou),1,10);
//  bottom-10 (cost,idx) lex pairs == dyn_k stable argmin passes.
// =====================================================================
#define TKB 256
__global__ void select_kernel()
{
    int b = blockIdx.x / G, g = blockIdx.x % G;
    const float* iou  = g_iou  + ((long long)b*G+g)*Q;
    const float* cost = g_cost + ((long long)b*G+g)*Q;
    int t = threadIdx.x;

    __shared__ float s_pv[TKB*10];
    __shared__ int   s_pi[TKB*10];
    __shared__ int   s_dynk;

    // ---- phase 1: top-10 iou (descending) ----
    {
        float top[10];
        #pragma unroll
        for (int i=0;i<10;i++) top[i] = -INFINITY;
        for (int q=t; q<Q; q+=TKB) {
            float v = iou[q];
            if (v > top[9]) {
                int i = 9;
                while (i>0 && top[i-1] < v) { top[i]=top[i-1]; i--; }
                top[i] = v;
            }
        }
        #pragma unroll
        for (int i=0;i<10;i++) s_pv[t*10+i] = top[i];
        __syncthreads();
        for (int s=TKB/2; s>=1; s>>=1) {
            if (t < s) {
                float a[10], c[10], m[10];
                #pragma unroll
                for (int i=0;i<10;i++){ a[i]=s_pv[t*10+i]; c[i]=s_pv[(t+s)*10+i]; }
                int ia=0, ic=0;
                #pragma unroll
                for (int i=0;i<10;i++) m[i] = (a[ia] >= c[ic]) ? a[ia++] : c[ic++];
                #pragma unroll
                for (int i=0;i<10;i++) s_pv[t*10+i] = m[i];
            }
            __syncthreads();
        }
        if (t==0) {
            float ssum = 0.0f;
            for (int i=0;i<10;i++) ssum += s_pv[i];
            int k = (int)ssum;     // trunc toward zero
            if (k < 1) k = 1;
            if (k > 10) k = 10;
            s_dynk = k;
        }
        __syncthreads();
    }

    // ---- phase 2: bottom-10 (cost, idx) lexicographic ----
    {
        float pv[10]; int pi[10];
        #pragma unroll
        for (int i=0;i<10;i++) { pv[i] = INFINITY; pi[i] = 0x7FFFFFFF; }
        for (int q=t; q<Q; q+=TKB) {
            float v = cost[q];
            // ascending scan: strict < on value suffices for lex insert
            if (v < pv[9]) {
                int i = 9;
                while (i>0 && v < pv[i-1]) { pv[i]=pv[i-1]; pi[i]=pi[i-1]; i--; }
                pv[i]=v; pi[i]=q;
            }
        }
        #pragma unroll
        for (int i=0;i<10;i++) { s_pv[t*10+i]=pv[i]; s_pi[t*10+i]=pi[i]; }
        __syncthreads();
        for (int s=TKB/2; s>=1; s>>=1) {
            if (t < s) {
                float av[10], bv[10], mv[10];
                int   ai[10], bi[10], mi[10];
                #pragma unroll
                for (int i=0;i<10;i++){
                    av[i]=s_pv[t*10+i];     ai[i]=s_pi[t*10+i];
                    bv[i]=s_pv[(t+s)*10+i]; bi[i]=s_pi[(t+s)*10+i];
                }
                int ia=0, ic=0;
                #pragma unroll
                for (int i=0;i<10;i++) {
                    bool takeA = (av[ia] < bv[ic]) ||
                                 (av[ia]==bv[ic] && ai[ia] < bi[ic]);
                    if (takeA) { mv[i]=av[ia]; mi[i]=ai[ia]; ia++; }
                    else       { mv[i]=bv[ic]; mi[i]=bi[ic]; ic++; }
                }
                #pragma unroll
                for (int i=0;i<10;i++){ s_pv[t*10+i]=mv[i]; s_pi[t*10+i]=mi[i]; }
            }
            __syncthreads();
        }
        if (t==0) {
            int k = s_dynk;
            for (int j=0; j<k; j++)
                atomicOr(&g_mask[b*Q + s_pi[j]], 1ULL<<g);
        }
    }
}

// =====================================================================
// Kernel C: per-image dedup + while-loop + outputs (1024 thr / image).
// =====================================================================
#define TD 1024
#define NW (TD/32)
__global__ void loop_kernel(char* __restrict__ out_bytes, int layoutB)
{
    int b = blockIdx.x, t = threadIdx.x;
    int wid = t/32, lane = t%32;
    unsigned long long* mask = g_mask + b*Q;
    float* pen = g_pen + b*Q;
    const float* cost = g_cost + (long long)b*G*Q;
    const int* rowarg = g_rowarg + b*Q;

    __shared__ int s_cnt[G];
    __shared__ int s_unm[G];
    __shared__ int s_n;
    __shared__ int s_fix;
    __shared__ unsigned char s_stale_chunk; // dummy
    __shared__ unsigned char s_stale[ (Q+TD-1)/TD > 0 ? 1 : 1 ]; // unused placeholder

    // prologue: dedup rows with >1 matches -> one-hot(rowarg); record stale
    // stale stored compactly: reuse g_pen sign? No — store in a per-row byte in
    // registers is impossible; use a bit in a shared/global array. Use a device
    // global region inside g_pen? pen must stay float. Use high bit of rowarg.
    for (int q=t; q<Q; q+=TD) {
        unsigned long long m = mask[q];
        if (__popcll(m) > 1) {
            mask[q] = 1ULL << (rowarg[q] & 63);
            // mark stale by setting bit 30 in g_rowarg (value < 64 normally)
            ((int*)g_rowarg)[b*Q+q] = (rowarg[q] & 63) | 0x40000000;
        }
    }
    __syncthreads();

    for (int iter=0; iter<20000; iter++) {
        if (t < G) s_cnt[t] = 0;
        if (t == 0) { s_n = 0; s_fix = 0; }
        __syncthreads();
        for (int q=t; q<Q; q+=TD) {
            unsigned long long m = mask[q];
            while (m) { int g = __ffsll((long long)m)-1; atomicAdd(&s_cnt[g],1); m &= m-1; }
        }
        __syncthreads();
        if (t < G && s_cnt[t] == 0) s_unm[atomicAdd(&s_n,1)] = t;
        __syncthreads();
        if (s_n == 0) break;

        // accumulate row penalty for matched rows
        for (int q=t; q<Q; q+=TD) if (mask[q]) pen[q] += 100000.0f;
        __syncthreads();

        // warp-parallel column argmins over unmatched columns
        for (int u = wid; u < s_n; u += NW) {
            int g = s_unm[u];
            const float* cg = cost + (long long)g*Q;
            float bv = INFINITY; int bi = Q;
            for (int q=lane; q<Q; q+=32) {
                float v = cg[q] + pen[q];
                if (v < bv) { bv=v; bi=q; }   // ascending q per lane: keeps lowest
            }
            #pragma unroll
            for (int off=16; off; off>>=1) {
                float ov = __shfl_down_sync(0xffffffff, bv, off);
                int   oi = __shfl_down_sync(0xffffffff, bi, off);
                if (ov < bv || (ov==bv && oi < bi)) { bv=ov; bi=oi; }
            }
            if (lane==0) atomicOr(&mask[bi], 1ULL<<g);
        }
        __syncthreads();

        // fix step
        for (int q=t; q<Q; q+=TD) if (__popcll(mask[q]) > 1) s_fix = 1;
        __syncthreads();
        if (s_fix) {
            for (int q=t; q<Q; q+=TD) {
                int ra = ((const int*)g_rowarg)[b*Q+q];
                if (ra & 0x40000000) mask[q] = 1ULL << (ra & 63);
            }
        }
        __syncthreads();
    }

    // ---- outputs ----
    if (layoutB) {
        unsigned char* out_sel = (unsigned char*)out_bytes;
        int* out_asn = (int*)(out_bytes + (size_t)BB*Q);
        int* out_mq  = (int*)(out_bytes + (size_t)BB*Q + (size_t)4*BB*Q);
        for (int q=t; q<Q; q+=TD) {
            unsigned long long m = mask[q];
            out_sel[b*Q+q] = m ? 1 : 0;
            out_asn[b*Q+q] = m ? (__ffsll((long long)m)-1) : 0;
        }
        for (int g=wid; g<G; g+=NW) {
            const float* cg = cost + (long long)g*Q;
            float bv = INFINITY; int bi = 0;
            for (int q=lane; q<Q; q+=32) {
                if ((mask[q]>>g) & 1ULL) {
                    float v = cg[q] + pen[q];
                    if (v < bv) { bv=v; bi=q; }
                }
            }
            #pragma unroll
            for (int off=16; off; off>>=1) {
                float ov = __shfl_down_sync(0xffffffff, bv, off);
                int   oi = __shfl_down_sync(0xffffffff, bi, off);
                if (ov < bv || (ov==bv && oi < bi)) { bv=ov; bi=oi; }
            }
            if (lane==0) out_mq[b*G+g] = bi;
        }
    } else {
        float* out = (float*)out_bytes;
        float* out_sel = out;
        float* out_asn = out + BB*Q;
        float* out_mq  = out + 2*BB*Q;
        for (int q=t; q<Q; q+=TD) {
            unsigned long long m = mask[q];
            out_sel[b*Q+q] = m ? 1.0f : 0.0f;
            out_asn[b*Q+q] = m ? (float)(__ffsll((long long)m)-1) : 0.0f;
        }
        for (int g=wid; g<G; g+=NW) {
            const float* cg = cost + (long long)g*Q;
            float bv = INFINITY; int bi = 0;
            for (int q=lane; q<Q; q+=32) {
                if ((mask[q]>>g) & 1ULL) {
                    float v = cg[q] + pen[q];
                    if (v < bv) { bv=v; bi=q; }
                }
            }
            #pragma unroll
            for (int off=16; off; off>>=1) {
                float ov = __shfl_down_sync(0xffffffff, bv, off);
                int   oi = __shfl_down_sync(0xffffffff, bi, off);
                if (ov < bv || (ov==bv && oi < bi)) { bv=ov; bi=oi; }
            }
            if (lane==0) out_mq[b*G+g] = (float)bi;
        }
    }
}

// =====================================================================
extern "C" void kernel_launch(void* const* d_in, const int* in_sizes, int n_in,
                              void* d_out, int out_size)
{
    const float* logits = 0; const float* boxes = 0;
    const int*   labels = 0; const float* gtb   = 0;
    for (int i = 0; i < n_in; i++) {
        switch (in_sizes[i]) {
            case BB*Q*CC: logits = (const float*)d_in[i]; break;
            case BB*Q*4:  boxes  = (const float*)d_in[i]; break;
            case BB*G:    labels = (const int*)  d_in[i]; break;
            case BB*G*4:  gtb    = (const float*)d_in[i]; break;
        }
    }

    int layoutB = (out_size == BB*Q + 4*BB*Q + 4*BB*G) ? 1 : 0;

    dim3 gA((Q + TA - 1)/TA, BB);
    build_cost_kernel<<<gA, TA>>>(logits, boxes, labels, gtb);
    select_kernel<<<BB*G, TKB>>>();
    loop_kernel<<<BB, TD>>>((char*)d_out, layoutB);
}